// round 3
// baseline (speedup 1.0000x reference)
#include <cuda_runtime.h>
#include <math.h>

typedef unsigned long long ull;

// ---------------------------------------------------------------------------
// Scratch (device globals — no allocation allowed)
// ---------------------------------------------------------------------------
__device__ ull   g_w1p[25 * 32];          // packed conv1 weights [k][coP] -> (w[2c],w[2c+1])
__device__ float g_b1[64];
__device__ ull   g_w2p[64 * 25 * 32];     // packed conv2 weights [ci][k][coP]
__device__ float g_b2[64];
__device__ float g_w3[10 * 1024];
__device__ float g_b3[10];
__device__ ull   g_pool1d[(size_t)2048 * 64 * 144]; // duplicated (v,v) pairs, 151 MB
__device__ float g_pool2[(size_t)2048 * 1024];      // 8.4 MB
__device__ float g_smax1[2048];
__device__ float g_max2[2048 * 64];
__device__ float g_stat1;
__device__ float g_stat2[64];
__device__ float g_stat3[1024];

// ---------------------------------------------------------------------------
// Helpers
// ---------------------------------------------------------------------------
__device__ __forceinline__ float warp_max(float v) {
    #pragma unroll
    for (int o = 16; o; o >>= 1) v = fmaxf(v, __shfl_xor_sync(0xFFFFFFFFu, v, o));
    return v;
}
__device__ __forceinline__ float warp_sum(float v) {
    #pragma unroll
    for (int o = 16; o; o >>= 1) v += __shfl_xor_sync(0xFFFFFFFFu, v, o);
    return v;
}

__device__ __forceinline__ float scinol_p(float p0, float S2, float G, float eta,
                                          float M, bool cond) {
    float denom = sqrtf(S2 + M * M);
    float theta = fminf(fmaxf(G / denom, -1.0f), 1.0f);
    float upd = cond ? theta / (2.0f * denom) * eta : 0.0f;
    return p0 + upd;
}

// Packed f32x2 FMA: d.lo += a.lo*b.lo ; d.hi += a.hi*b.hi
__device__ __forceinline__ void fma2(ull& d, ull a, ull b) {
    asm("fma.rn.f32x2 %0, %1, %2, %0;" : "+l"(d) : "l"(a), "l"(b));
}
__device__ __forceinline__ ull pack2(float lo, float hi) {
    return ((ull)__float_as_uint(hi) << 32) | (ull)__float_as_uint(lo);
}
__device__ __forceinline__ float unpack_lo(ull v) { return __uint_as_float((unsigned)v); }
__device__ __forceinline__ float unpack_hi(ull v) { return __uint_as_float((unsigned)(v >> 32)); }

// ---------------------------------------------------------------------------
// Stage 1: stat1 = mean_n( max_{h,w} |x[n,0,h,w]| )
// ---------------------------------------------------------------------------
__global__ void k_stat1_max(const float* __restrict__ x) {
    int n = blockIdx.x;
    const float* xp = x + (size_t)n * 784;
    float m = 0.0f;
    for (int i = threadIdx.x; i < 784; i += 256) m = fmaxf(m, fabsf(xp[i]));
    __shared__ float s[8];
    m = warp_max(m);
    if ((threadIdx.x & 31) == 0) s[threadIdx.x >> 5] = m;
    __syncthreads();
    if (threadIdx.x < 32) {
        float v = (threadIdx.x < 8) ? s[threadIdx.x] : 0.0f;
        v = warp_max(v);
        if (threadIdx.x == 0) g_smax1[n] = v;
    }
}

__global__ void k_stat1_mean() {
    float s = 0.0f;
    for (int i = threadIdx.x; i < 2048; i += 256) s += g_smax1[i];
    __shared__ float sm[8];
    s = warp_sum(s);
    if ((threadIdx.x & 31) == 0) sm[threadIdx.x >> 5] = s;
    __syncthreads();
    if (threadIdx.x < 32) {
        float v = (threadIdx.x < 8) ? sm[threadIdx.x] : 0.0f;
        v = warp_sum(v);
        if (threadIdx.x == 0) g_stat1 = v * (1.0f / 2048.0f);
    }
}

// ---------------------------------------------------------------------------
// Conv1 effective weights, packed over channel pairs: g_w1p[k*32+coP]
// ---------------------------------------------------------------------------
__global__ void k_w1(const float* __restrict__ w0, const float* __restrict__ wS2,
                     const float* __restrict__ wG, const float* __restrict__ weta,
                     const float* __restrict__ wM,
                     const float* __restrict__ b0, const float* __restrict__ bS2,
                     const float* __restrict__ bG, const float* __restrict__ beta) {
    float M = fmaxf(g_stat1, wM[0]);
    int tot = gridDim.x * blockDim.x;
    int gid = blockIdx.x * blockDim.x + threadIdx.x;
    for (int p = gid; p < 800; p += tot) {
        int k = p >> 5, coP = p & 31;
        int iL = (2 * coP) * 25 + k;
        int iH = (2 * coP + 1) * 25 + k;
        float lo = scinol_p(w0[iL], wS2[iL], wG[iL], weta[iL], M, wG[iL] != 0.0f);
        float hi = scinol_p(w0[iH], wS2[iH], wG[iH], weta[iH], M, wG[iH] != 0.0f);
        g_w1p[p] = pack2(lo, hi);
    }
    for (int i = gid; i < 64; i += tot)
        g_b1[i] = scinol_p(b0[i], bS2[i], bG[i], beta[i], 1.0f, bG[i] != 0.0f);
}

// ---------------------------------------------------------------------------
// Conv1 + ReLU + 2x2 maxpool, f32x2 over output-channel pairs.
// Writes pool1 as duplicated (v,v) ull pairs for conv2's packed consumption.
// ---------------------------------------------------------------------------
__global__ void __launch_bounds__(128, 4) k_conv1(const float* __restrict__ x) {
    __shared__ ull xs2[784];   // (v,v) pairs, 6.3 KB
    __shared__ ull ws[800];    // packed weights, 6.4 KB
    int n = blockIdx.x;
    int tid = threadIdx.x;
    const float* xp = x + (size_t)n * 784;
    for (int i = tid; i < 784; i += 128) {
        float v = xp[i];
        xs2[i] = pack2(v, v);
    }
    for (int i = tid; i < 800; i += 128) ws[i] = g_w1p[i];
    __syncthreads();

    int coP = tid >> 2, q = tid & 3;
    float bL = g_b1[2 * coP], bH = g_b1[2 * coP + 1];
    float cmaxL = 0.0f, cmaxH = 0.0f;
    ull* outL = g_pool1d + ((size_t)n * 64 + 2 * coP) * 144;
    ull* outH = outL + 144;

    for (int t = q; t < 36; t += 4) {
        int tr = t / 6, tc = t - tr * 6;
        const ull* xc = xs2 + (tr * 4) * 28 + tc * 4;   // 16B-aligned
        ull X[4][8];
        #pragma unroll
        for (int r = 0; r < 4; r++)
            #pragma unroll
            for (int c2 = 0; c2 < 4; c2++) {
                ulonglong2 v2 = *(const ulonglong2*)(xc + r * 28 + 2 * c2);
                X[r][2 * c2] = v2.x;
                X[r][2 * c2 + 1] = v2.y;
            }
        ull acc[4][4];
        #pragma unroll
        for (int i = 0; i < 4; i++)
            #pragma unroll
            for (int j = 0; j < 4; j++) acc[i][j] = 0ULL;

        #pragma unroll
        for (int ky = 0; ky < 5; ky++) {
            ull w[5];
            #pragma unroll
            for (int kx = 0; kx < 5; kx++)
                w[kx] = ws[(ky * 5 + kx) * 32 + coP];
            #pragma unroll
            for (int kx = 0; kx < 5; kx++)
                #pragma unroll
                for (int i = 0; i < 4; i++)
                    #pragma unroll
                    for (int j = 0; j < 4; j++)
                        fma2(acc[i][j], w[kx], X[(ky + i) & 3][j + kx]);
            if (ky < 4) {
                #pragma unroll
                for (int c2 = 0; c2 < 4; c2++) {
                    ulonglong2 v2 = *(const ulonglong2*)(xc + (ky + 4) * 28 + 2 * c2);
                    X[ky & 3][2 * c2] = v2.x;
                    X[ky & 3][2 * c2 + 1] = v2.y;
                }
            }
        }

        #pragma unroll
        for (int pi = 0; pi < 2; pi++)
            #pragma unroll
            for (int pj = 0; pj < 2; pj++) {
                float mL = fmaxf(fmaxf(unpack_lo(acc[2*pi][2*pj]),   unpack_lo(acc[2*pi][2*pj+1])),
                                 fmaxf(unpack_lo(acc[2*pi+1][2*pj]), unpack_lo(acc[2*pi+1][2*pj+1])));
                float mH = fmaxf(fmaxf(unpack_hi(acc[2*pi][2*pj]),   unpack_hi(acc[2*pi][2*pj+1])),
                                 fmaxf(unpack_hi(acc[2*pi+1][2*pj]), unpack_hi(acc[2*pi+1][2*pj+1])));
                float vL = fmaxf(mL + bL, 0.0f);
                float vH = fmaxf(mH + bH, 0.0f);
                int off = (tr * 2 + pi) * 12 + (tc * 2 + pj);
                outL[off] = pack2(vL, vL);
                outH[off] = pack2(vH, vH);
                cmaxL = fmaxf(cmaxL, vL);
                cmaxH = fmaxf(cmaxH, vH);
            }
    }
    cmaxL = fmaxf(cmaxL, __shfl_xor_sync(0xFFFFFFFFu, cmaxL, 1));
    cmaxL = fmaxf(cmaxL, __shfl_xor_sync(0xFFFFFFFFu, cmaxL, 2));
    cmaxH = fmaxf(cmaxH, __shfl_xor_sync(0xFFFFFFFFu, cmaxH, 1));
    cmaxH = fmaxf(cmaxH, __shfl_xor_sync(0xFFFFFFFFu, cmaxH, 2));
    if (q == 0) {
        g_max2[n * 64 + 2 * coP] = cmaxL;
        g_max2[n * 64 + 2 * coP + 1] = cmaxH;
    }
}

// ---------------------------------------------------------------------------
// stat2[c] = mean_n g_max2[n][c]
// ---------------------------------------------------------------------------
__global__ void k_stat2() {
    int c = blockIdx.x;
    float s = 0.0f;
    for (int i = threadIdx.x; i < 2048; i += 256) s += g_max2[i * 64 + c];
    __shared__ float sm[8];
    s = warp_sum(s);
    if ((threadIdx.x & 31) == 0) sm[threadIdx.x >> 5] = s;
    __syncthreads();
    if (threadIdx.x < 32) {
        float v = (threadIdx.x < 8) ? sm[threadIdx.x] : 0.0f;
        v = warp_sum(v);
        if (threadIdx.x == 0) g_stat2[c] = v * (1.0f / 2048.0f);
    }
}

// ---------------------------------------------------------------------------
// Conv2 effective weights, packed: g_w2p[(ci*25+k)*32 + coP]
// ---------------------------------------------------------------------------
__global__ void k_w2(const float* __restrict__ w0, const float* __restrict__ wS2,
                     const float* __restrict__ wG, const float* __restrict__ weta,
                     const float* __restrict__ wM,
                     const float* __restrict__ b0, const float* __restrict__ bS2,
                     const float* __restrict__ bG, const float* __restrict__ beta) {
    int tot = gridDim.x * blockDim.x;
    int gid = blockIdx.x * blockDim.x + threadIdx.x;
    for (int p = gid; p < 51200; p += tot) {
        int coP = p & 31;
        int t = p >> 5;
        int k = t % 25, ci = t / 25;
        float M = fmaxf(g_stat2[ci], wM[ci]);
        int iL = ((2 * coP) * 64 + ci) * 25 + k;
        int iH = ((2 * coP + 1) * 64 + ci) * 25 + k;
        float lo = scinol_p(w0[iL], wS2[iL], wG[iL], weta[iL], M, wG[iL] != 0.0f);
        float hi = scinol_p(w0[iH], wS2[iH], wG[iH], weta[iH], M, wG[iH] != 0.0f);
        g_w2p[p] = pack2(lo, hi);
    }
    for (int i = gid; i < 64; i += tot)
        g_b2[i] = scinol_p(b0[i], bS2[i], bG[i], beta[i], 1.0f, bG[i] != 0.0f);
}

// ---------------------------------------------------------------------------
// Conv2 + ReLU + 2x2 maxpool, f32x2 over output-channel pairs.
// Input staged from pre-duplicated g_pool1d in 16-channel double-buffered
// smem chunks (2 x 18 KB). 128 threads: coP = tid>>2, quad = tid&3.
// ---------------------------------------------------------------------------
__global__ void __launch_bounds__(128, 4) k_conv2() {
    __shared__ ull buf[2][2304];   // 16 ci x 144 pairs per buffer
    int n = blockIdx.x;
    int tid = threadIdx.x;
    const ull* src = g_pool1d + (size_t)n * 9216;

    {   // load chunk 0
        const ulonglong2* s2 = (const ulonglong2*)src;
        ulonglong2* d2 = (ulonglong2*)buf[0];
        for (int i = tid; i < 1152; i += 128) d2[i] = s2[i];
    }
    __syncthreads();

    int coP = tid >> 2, q = tid & 3;
    int ty = q >> 1, tx = q & 1;
    ull acc[4][4];
    #pragma unroll
    for (int i = 0; i < 4; i++)
        #pragma unroll
        for (int j = 0; j < 4; j++) acc[i][j] = 0ULL;

    const ull* wbase = g_w2p + coP;
    int xoff = (ty * 4) * 12 + tx * 4;

    for (int c = 0; c < 4; c++) {
        // prefetch next chunk into the other buffer (overlaps with compute)
        if (c < 3) {
            const ulonglong2* s2 = (const ulonglong2*)(src + (c + 1) * 2304);
            ulonglong2* d2 = (ulonglong2*)buf[(c + 1) & 1];
            #pragma unroll
            for (int i = 0; i < 9; i++) d2[tid + i * 128] = s2[tid + i * 128];
        }
        const ull* bp = buf[c & 1];
        for (int cil = 0; cil < 16; cil++) {
            const ull* xc = bp + cil * 144 + xoff;                 // 16B-aligned
            const ull* wc = wbase + ((c * 16 + cil) * 25) * 32;
            ull X[4][8];
            #pragma unroll
            for (int r = 0; r < 4; r++)
                #pragma unroll
                for (int c2 = 0; c2 < 4; c2++) {
                    ulonglong2 v2 = *(const ulonglong2*)(xc + r * 12 + 2 * c2);
                    X[r][2 * c2] = v2.x;
                    X[r][2 * c2 + 1] = v2.y;
                }
            #pragma unroll
            for (int ky = 0; ky < 5; ky++) {
                ull w[5];
                #pragma unroll
                for (int kx = 0; kx < 5; kx++)
                    w[kx] = __ldg(wc + (ky * 5 + kx) * 32);
                #pragma unroll
                for (int kx = 0; kx < 5; kx++)
                    #pragma unroll
                    for (int i = 0; i < 4; i++)
                        #pragma unroll
                        for (int j = 0; j < 4; j++)
                            fma2(acc[i][j], w[kx], X[(ky + i) & 3][j + kx]);
                if (ky < 4) {
                    #pragma unroll
                    for (int c2 = 0; c2 < 4; c2++) {
                        ulonglong2 v2 = *(const ulonglong2*)(xc + (ky + 4) * 12 + 2 * c2);
                        X[ky & 3][2 * c2] = v2.x;
                        X[ky & 3][2 * c2 + 1] = v2.y;
                    }
                }
            }
        }
        __syncthreads();
    }

    float bL = __ldg(g_b2 + 2 * coP), bH = __ldg(g_b2 + 2 * coP + 1);
    float* outp = g_pool2 + (size_t)n * 1024;
    #pragma unroll
    for (int pi = 0; pi < 2; pi++)
        #pragma unroll
        for (int pj = 0; pj < 2; pj++) {
            float mL = fmaxf(fmaxf(unpack_lo(acc[2*pi][2*pj]),   unpack_lo(acc[2*pi][2*pj+1])),
                             fmaxf(unpack_lo(acc[2*pi+1][2*pj]), unpack_lo(acc[2*pi+1][2*pj+1])));
            float mH = fmaxf(fmaxf(unpack_hi(acc[2*pi][2*pj]),   unpack_hi(acc[2*pi][2*pj+1])),
                             fmaxf(unpack_hi(acc[2*pi+1][2*pj]), unpack_hi(acc[2*pi+1][2*pj+1])));
            float vL = fmaxf(mL + bL, 0.0f);
            float vH = fmaxf(mH + bH, 0.0f);
            int py = ty * 2 + pi, px = tx * 2 + pj;
            outp[(2 * coP) * 16 + py * 4 + px] = vL;
            outp[(2 * coP + 1) * 16 + py * 4 + px] = vH;
        }
}

// ---------------------------------------------------------------------------
// stat3[f] = mean_n pool2[n][f]   (values >= 0, |.| is identity)
// ---------------------------------------------------------------------------
__global__ void k_stat3() {
    int f = blockIdx.x * 32 + threadIdx.x;
    float s = 0.0f;
    for (int nidx = threadIdx.y; nidx < 2048; nidx += 8)
        s += g_pool2[(size_t)nidx * 1024 + f];
    __shared__ float sm[8][32];
    sm[threadIdx.y][threadIdx.x] = s;
    __syncthreads();
    if (threadIdx.y == 0) {
        float tot = 0.0f;
        #pragma unroll
        for (int r = 0; r < 8; r++) tot += sm[r][threadIdx.x];
        g_stat3[f] = tot * (1.0f / 2048.0f);
    }
}

// ---------------------------------------------------------------------------
// Linear effective weights (cond is wS2!=0 / bS2!=0; M = max(wM, stat3[f]))
// ---------------------------------------------------------------------------
__global__ void k_w3(const float* __restrict__ w0, const float* __restrict__ wS2,
                     const float* __restrict__ wG, const float* __restrict__ weta,
                     const float* __restrict__ wM,
                     const float* __restrict__ b0, const float* __restrict__ bS2,
                     const float* __restrict__ bG, const float* __restrict__ beta) {
    int tot = gridDim.x * blockDim.x;
    int gid = blockIdx.x * blockDim.x + threadIdx.x;
    for (int i = gid; i < 10240; i += tot) {
        int f = i & 1023;
        float M = fmaxf(wM[i], g_stat3[f]);
        g_w3[i] = scinol_p(w0[i], wS2[i], wG[i], weta[i], M, wS2[i] != 0.0f);
    }
    for (int i = gid; i < 10; i += tot)
        g_b3[i] = scinol_p(b0[i], bS2[i], bG[i], beta[i], 1.0f, bS2[i] != 0.0f);
}

// ---------------------------------------------------------------------------
// Linear: out[n][o] = pool2[n] . w3[o] + b3[o]. Block = sample, warp = output.
// ---------------------------------------------------------------------------
__global__ void __launch_bounds__(320) k_linear(float* __restrict__ out) {
    __shared__ float hs[1024];
    int n = blockIdx.x;
    int tid = threadIdx.x;
    const float* src = g_pool2 + (size_t)n * 1024;
    for (int i = tid; i < 1024; i += 320) hs[i] = src[i];
    __syncthreads();
    int w = tid >> 5, lane = tid & 31;
    const float* wr = g_w3 + w * 1024;
    float s = 0.0f;
    #pragma unroll 8
    for (int k = lane; k < 1024; k += 32) s = fmaf(hs[k], wr[k], s);
    s = warp_sum(s);
    if (lane == 0) out[n * 10 + w] = s + g_b3[w];
}

// ---------------------------------------------------------------------------
// Launch
// ---------------------------------------------------------------------------
extern "C" void kernel_launch(void* const* d_in, const int* in_sizes, int n_in,
                              void* d_out, int out_size) {
    const float* x = (const float*)d_in[0];
    const float* c1_w0 = (const float*)d_in[1];
    const float* c1_wS2 = (const float*)d_in[2];
    const float* c1_wG = (const float*)d_in[3];
    const float* c1_weta = (const float*)d_in[4];
    const float* c1_wM = (const float*)d_in[5];
    const float* c1_b0 = (const float*)d_in[6];
    const float* c1_bS2 = (const float*)d_in[7];
    const float* c1_bG = (const float*)d_in[8];
    const float* c1_beta = (const float*)d_in[9];
    const float* c2_w0 = (const float*)d_in[10];
    const float* c2_wS2 = (const float*)d_in[11];
    const float* c2_wG = (const float*)d_in[12];
    const float* c2_weta = (const float*)d_in[13];
    const float* c2_wM = (const float*)d_in[14];
    const float* c2_b0 = (const float*)d_in[15];
    const float* c2_bS2 = (const float*)d_in[16];
    const float* c2_bG = (const float*)d_in[17];
    const float* c2_beta = (const float*)d_in[18];
    const float* l_w0 = (const float*)d_in[19];
    const float* l_wS2 = (const float*)d_in[20];
    const float* l_wG = (const float*)d_in[21];
    const float* l_weta = (const float*)d_in[22];
    const float* l_wM = (const float*)d_in[23];
    const float* l_b0 = (const float*)d_in[24];
    const float* l_bS2 = (const float*)d_in[25];
    const float* l_bG = (const float*)d_in[26];
    const float* l_beta = (const float*)d_in[27];
    float* out = (float*)d_out;

    k_stat1_max<<<2048, 256>>>(x);
    k_stat1_mean<<<1, 256>>>();
    k_w1<<<8, 256>>>(c1_w0, c1_wS2, c1_wG, c1_weta, c1_wM, c1_b0, c1_bS2, c1_bG, c1_beta);
    k_conv1<<<2048, 128>>>(x);
    k_stat2<<<64, 256>>>();
    k_w2<<<128, 256>>>(c2_w0, c2_wS2, c2_wG, c2_weta, c2_wM, c2_b0, c2_bS2, c2_bG, c2_beta);
    k_conv2<<<2048, 128>>>();
    k_stat3<<<32, dim3(32, 8)>>>();
    k_w3<<<48, 256>>>(l_w0, l_wS2, l_wG, l_weta, l_wM, l_b0, l_bS2, l_bG, l_beta);
    k_linear<<<2048, 320>>>(out);
}

// round 4
// speedup vs baseline: 1.0380x; 1.0380x over previous
#include <cuda_runtime.h>
#include <math.h>

typedef unsigned long long ull;

// ---------------------------------------------------------------------------
// Scratch (device globals — no allocation allowed)
// ---------------------------------------------------------------------------
__device__ ull   g_w1p[25 * 32];          // packed conv1 weights [k][coP]
__device__ float g_b1[64];
__device__ ull   g_w2p[2 * 64 * 25 * 16]; // packed conv2 weights [grp][ci][k][coPin]
__device__ float g_b2[64];
__device__ float g_w3[10 * 1024];
__device__ float g_b3[10];
__device__ float g_pool1[(size_t)2048 * 64 * 144];  // 75.5 MB (plain float)
__device__ float g_pool2[(size_t)2048 * 1024];      // 8.4 MB
__device__ float g_smax1[2048];
__device__ float g_max2[2048 * 64];
__device__ float g_stat1;
__device__ float g_stat2[64];
__device__ float g_stat3[1024];

// ---------------------------------------------------------------------------
// Helpers
// ---------------------------------------------------------------------------
__device__ __forceinline__ float warp_max(float v) {
    #pragma unroll
    for (int o = 16; o; o >>= 1) v = fmaxf(v, __shfl_xor_sync(0xFFFFFFFFu, v, o));
    return v;
}
__device__ __forceinline__ float warp_sum(float v) {
    #pragma unroll
    for (int o = 16; o; o >>= 1) v += __shfl_xor_sync(0xFFFFFFFFu, v, o);
    return v;
}

__device__ __forceinline__ float scinol_p(float p0, float S2, float G, float eta,
                                          float M, bool cond) {
    float denom = sqrtf(S2 + M * M);
    float theta = fminf(fmaxf(G / denom, -1.0f), 1.0f);
    float upd = cond ? theta / (2.0f * denom) * eta : 0.0f;
    return p0 + upd;
}

__device__ __forceinline__ void fma2(ull& d, ull a, ull b) {
    asm("fma.rn.f32x2 %0, %1, %2, %0;" : "+l"(d) : "l"(a), "l"(b));
}
__device__ __forceinline__ ull pack2(float lo, float hi) {
    return ((ull)__float_as_uint(hi) << 32) | (ull)__float_as_uint(lo);
}
__device__ __forceinline__ float unpack_lo(ull v) { return __uint_as_float((unsigned)v); }
__device__ __forceinline__ float unpack_hi(ull v) { return __uint_as_float((unsigned)(v >> 32)); }

// ---------------------------------------------------------------------------
// Stage 1: stat1 = mean_n( max_{h,w} |x[n,0,h,w]| )
// ---------------------------------------------------------------------------
__global__ void k_stat1_max(const float* __restrict__ x) {
    int n = blockIdx.x;
    const float* xp = x + (size_t)n * 784;
    float m = 0.0f;
    for (int i = threadIdx.x; i < 784; i += 256) m = fmaxf(m, fabsf(xp[i]));
    __shared__ float s[8];
    m = warp_max(m);
    if ((threadIdx.x & 31) == 0) s[threadIdx.x >> 5] = m;
    __syncthreads();
    if (threadIdx.x < 32) {
        float v = (threadIdx.x < 8) ? s[threadIdx.x] : 0.0f;
        v = warp_max(v);
        if (threadIdx.x == 0) g_smax1[n] = v;
    }
}

__global__ void k_stat1_mean() {
    float s = 0.0f;
    for (int i = threadIdx.x; i < 2048; i += 256) s += g_smax1[i];
    __shared__ float sm[8];
    s = warp_sum(s);
    if ((threadIdx.x & 31) == 0) sm[threadIdx.x >> 5] = s;
    __syncthreads();
    if (threadIdx.x < 32) {
        float v = (threadIdx.x < 8) ? sm[threadIdx.x] : 0.0f;
        v = warp_sum(v);
        if (threadIdx.x == 0) g_stat1 = v * (1.0f / 2048.0f);
    }
}

// ---------------------------------------------------------------------------
// Conv1 effective weights, packed over channel pairs: g_w1p[k*32+coP]
// ---------------------------------------------------------------------------
__global__ void k_w1(const float* __restrict__ w0, const float* __restrict__ wS2,
                     const float* __restrict__ wG, const float* __restrict__ weta,
                     const float* __restrict__ wM,
                     const float* __restrict__ b0, const float* __restrict__ bS2,
                     const float* __restrict__ bG, const float* __restrict__ beta) {
    float M = fmaxf(g_stat1, wM[0]);
    int tot = gridDim.x * blockDim.x;
    int gid = blockIdx.x * blockDim.x + threadIdx.x;
    for (int p = gid; p < 800; p += tot) {
        int k = p >> 5, coP = p & 31;
        int iL = (2 * coP) * 25 + k;
        int iH = (2 * coP + 1) * 25 + k;
        float lo = scinol_p(w0[iL], wS2[iL], wG[iL], weta[iL], M, wG[iL] != 0.0f);
        float hi = scinol_p(w0[iH], wS2[iH], wG[iH], weta[iH], M, wG[iH] != 0.0f);
        g_w1p[p] = pack2(lo, hi);
    }
    for (int i = gid; i < 64; i += tot)
        g_b1[i] = scinol_p(b0[i], bS2[i], bG[i], beta[i], 1.0f, bG[i] != 0.0f);
}

// ---------------------------------------------------------------------------
// Conv1 + ReLU + 2x2 maxpool, f32x2 over output-channel pairs. Writes float.
// ---------------------------------------------------------------------------
__global__ void __launch_bounds__(128, 4) k_conv1(const float* __restrict__ x) {
    __shared__ ull xs2[784];   // (v,v) pairs
    __shared__ ull ws[800];    // packed weights
    int n = blockIdx.x;
    int tid = threadIdx.x;
    const float* xp = x + (size_t)n * 784;
    for (int i = tid; i < 784; i += 128) {
        float v = xp[i];
        xs2[i] = pack2(v, v);
    }
    for (int i = tid; i < 800; i += 128) ws[i] = g_w1p[i];
    __syncthreads();

    int coP = tid >> 2, q = tid & 3;
    float bL = g_b1[2 * coP], bH = g_b1[2 * coP + 1];
    float cmaxL = 0.0f, cmaxH = 0.0f;
    float* outL = g_pool1 + ((size_t)n * 64 + 2 * coP) * 144;
    float* outH = outL + 144;

    for (int t = q; t < 36; t += 4) {
        int tr = t / 6, tc = t - tr * 6;
        const ull* xc = xs2 + (tr * 4) * 28 + tc * 4;
        ull X[4][8];
        #pragma unroll
        for (int r = 0; r < 4; r++)
            #pragma unroll
            for (int c2 = 0; c2 < 4; c2++) {
                ulonglong2 v2 = *(const ulonglong2*)(xc + r * 28 + 2 * c2);
                X[r][2 * c2] = v2.x;
                X[r][2 * c2 + 1] = v2.y;
            }
        ull acc[4][4];
        #pragma unroll
        for (int i = 0; i < 4; i++)
            #pragma unroll
            for (int j = 0; j < 4; j++) acc[i][j] = 0ULL;

        #pragma unroll
        for (int ky = 0; ky < 5; ky++) {
            ull w[5];
            #pragma unroll
            for (int kx = 0; kx < 5; kx++)
                w[kx] = ws[(ky * 5 + kx) * 32 + coP];
            #pragma unroll
            for (int kx = 0; kx < 5; kx++)
                #pragma unroll
                for (int i = 0; i < 4; i++)
                    #pragma unroll
                    for (int j = 0; j < 4; j++)
                        fma2(acc[i][j], w[kx], X[(ky + i) & 3][j + kx]);
            if (ky < 4) {
                #pragma unroll
                for (int c2 = 0; c2 < 4; c2++) {
                    ulonglong2 v2 = *(const ulonglong2*)(xc + (ky + 4) * 28 + 2 * c2);
                    X[ky & 3][2 * c2] = v2.x;
                    X[ky & 3][2 * c2 + 1] = v2.y;
                }
            }
        }

        #pragma unroll
        for (int pi = 0; pi < 2; pi++)
            #pragma unroll
            for (int pj = 0; pj < 2; pj++) {
                float mL = fmaxf(fmaxf(unpack_lo(acc[2*pi][2*pj]),   unpack_lo(acc[2*pi][2*pj+1])),
                                 fmaxf(unpack_lo(acc[2*pi+1][2*pj]), unpack_lo(acc[2*pi+1][2*pj+1])));
                float mH = fmaxf(fmaxf(unpack_hi(acc[2*pi][2*pj]),   unpack_hi(acc[2*pi][2*pj+1])),
                                 fmaxf(unpack_hi(acc[2*pi+1][2*pj]), unpack_hi(acc[2*pi+1][2*pj+1])));
                float vL = fmaxf(mL + bL, 0.0f);
                float vH = fmaxf(mH + bH, 0.0f);
                int off = (tr * 2 + pi) * 12 + (tc * 2 + pj);
                outL[off] = vL;
                outH[off] = vH;
                cmaxL = fmaxf(cmaxL, vL);
                cmaxH = fmaxf(cmaxH, vH);
            }
    }
    cmaxL = fmaxf(cmaxL, __shfl_xor_sync(0xFFFFFFFFu, cmaxL, 1));
    cmaxL = fmaxf(cmaxL, __shfl_xor_sync(0xFFFFFFFFu, cmaxL, 2));
    cmaxH = fmaxf(cmaxH, __shfl_xor_sync(0xFFFFFFFFu, cmaxH, 1));
    cmaxH = fmaxf(cmaxH, __shfl_xor_sync(0xFFFFFFFFu, cmaxH, 2));
    if (q == 0) {
        g_max2[n * 64 + 2 * coP] = cmaxL;
        g_max2[n * 64 + 2 * coP + 1] = cmaxH;
    }
}

// ---------------------------------------------------------------------------
// stat2[c] = mean_n g_max2[n][c]
// ---------------------------------------------------------------------------
__global__ void k_stat2() {
    int c = blockIdx.x;
    float s = 0.0f;
    for (int i = threadIdx.x; i < 2048; i += 256) s += g_max2[i * 64 + c];
    __shared__ float sm[8];
    s = warp_sum(s);
    if ((threadIdx.x & 31) == 0) sm[threadIdx.x >> 5] = s;
    __syncthreads();
    if (threadIdx.x < 32) {
        float v = (threadIdx.x < 8) ? sm[threadIdx.x] : 0.0f;
        v = warp_sum(v);
        if (threadIdx.x == 0) g_stat2[c] = v * (1.0f / 2048.0f);
    }
}

// ---------------------------------------------------------------------------
// Conv2 effective weights: g_w2p[((grp*64+ci)*25+k)*16 + coPin]
// (coP = grp*16+coPin; output channels 2*coP, 2*coP+1)
// ---------------------------------------------------------------------------
__global__ void k_w2(const float* __restrict__ w0, const float* __restrict__ wS2,
                     const float* __restrict__ wG, const float* __restrict__ weta,
                     const float* __restrict__ wM,
                     const float* __restrict__ b0, const float* __restrict__ bS2,
                     const float* __restrict__ bG, const float* __restrict__ beta) {
    int tot = gridDim.x * blockDim.x;
    int gid = blockIdx.x * blockDim.x + threadIdx.x;
    for (int p = gid; p < 51200; p += tot) {
        int coPin = p & 15;
        int t = p >> 4;
        int k = t % 25;
        int t2 = t / 25;
        int ci = t2 & 63, grp = t2 >> 6;
        int coP = grp * 16 + coPin;
        float M = fmaxf(g_stat2[ci], wM[ci]);
        int iL = ((2 * coP) * 64 + ci) * 25 + k;
        int iH = ((2 * coP + 1) * 64 + ci) * 25 + k;
        float lo = scinol_p(w0[iL], wS2[iL], wG[iL], weta[iL], M, wG[iL] != 0.0f);
        float hi = scinol_p(w0[iH], wS2[iH], wG[iH], weta[iH], M, wG[iH] != 0.0f);
        g_w2p[p] = pack2(lo, hi);
    }
    for (int i = gid; i < 64; i += tot)
        g_b2[i] = scinol_p(b0[i], bS2[i], bG[i], beta[i], 1.0f, bG[i] != 0.0f);
}

// ---------------------------------------------------------------------------
// Conv2 + ReLU + 2x2 maxpool. Block = 2 samples x 16 coP-pairs x 4 quads.
// ci in 8-channel chunks; weights AND input staged in smem. Input rows padded
// to stride 14 ull -> conflict-free quad LDS.128. Weights consumed via LDS.
// ---------------------------------------------------------------------------
__global__ void __launch_bounds__(128, 4) k_conv2() {
    __shared__ ull wsm[8 * 25 * 16];   // 3200 ull = 25.6 KB
    __shared__ ull xsm[2 * 8 * 168];   // 2688 ull = 21.5 KB (12 rows, stride 14)
    int bi = blockIdx.x;
    int n2 = bi >> 1, grp = bi & 1;
    int tid = threadIdx.x;
    int s = tid >> 6, rem = tid & 63;
    int coPl = rem >> 2, q = rem & 3;
    int ty = q >> 1, tx = q & 1;

    const ull* wsrc = g_w2p + (size_t)grp * 64 * 25 * 16;
    const float* xsrc = g_pool1 + (size_t)(n2 * 2) * 9216;

    ull acc[4][4];
    #pragma unroll
    for (int i = 0; i < 4; i++)
        #pragma unroll
        for (int j = 0; j < 4; j++) acc[i][j] = 0ULL;

    for (int c = 0; c < 8; c++) {
        __syncthreads();
        // stage weights chunk (contiguous, LDG.128 bulk)
        {
            const ulonglong2* s2 = (const ulonglong2*)(wsrc + c * 3200);
            ulonglong2* d2 = (ulonglong2*)wsm;
            #pragma unroll
            for (int i = 0; i < 13; i++) {
                int idx = tid + i * 128;
                if (idx < 1600) d2[idx] = s2[idx];
            }
        }
        // stage input chunk: 2 samples x 8 ci x 144 floats -> (v,v) pairs, stride 14
        for (int i = tid; i < 2304; i += 128) {
            int ss = i / 1152;
            int r = i - ss * 1152;
            int cil = r / 144;
            int p = r - cil * 144;
            int row = p / 12, col = p - row * 12;
            float v = xsrc[(size_t)ss * 9216 + (c * 8 + cil) * 144 + p];
            xsm[ss * 1344 + cil * 168 + row * 14 + col] = pack2(v, v);
        }
        __syncthreads();

        const ull* xb = xsm + s * 1344 + ty * 56 + tx * 4;
        #pragma unroll 1
        for (int cil = 0; cil < 8; cil++) {
            const ull* xc = xb + cil * 168;
            const ull* wc = wsm + cil * 400 + coPl;
            ull X[4][8];
            #pragma unroll
            for (int r = 0; r < 4; r++)
                #pragma unroll
                for (int c2 = 0; c2 < 4; c2++) {
                    ulonglong2 v2 = *(const ulonglong2*)(xc + r * 14 + 2 * c2);
                    X[r][2 * c2] = v2.x;
                    X[r][2 * c2 + 1] = v2.y;
                }
            #pragma unroll
            for (int ky = 0; ky < 5; ky++) {
                ull w[5];
                #pragma unroll
                for (int kx = 0; kx < 5; kx++)
                    w[kx] = wc[(ky * 5 + kx) * 16];
                #pragma unroll
                for (int kx = 0; kx < 5; kx++)
                    #pragma unroll
                    for (int i = 0; i < 4; i++)
                        #pragma unroll
                        for (int j = 0; j < 4; j++)
                            fma2(acc[i][j], w[kx], X[(ky + i) & 3][j + kx]);
                if (ky < 4) {
                    #pragma unroll
                    for (int c2 = 0; c2 < 4; c2++) {
                        ulonglong2 v2 = *(const ulonglong2*)(xc + (ky + 4) * 14 + 2 * c2);
                        X[ky & 3][2 * c2] = v2.x;
                        X[ky & 3][2 * c2 + 1] = v2.y;
                    }
                }
            }
        }
    }

    int coP = grp * 16 + coPl;
    float bL = __ldg(g_b2 + 2 * coP), bH = __ldg(g_b2 + 2 * coP + 1);
    float* outp = g_pool2 + (size_t)(n2 * 2 + s) * 1024;
    #pragma unroll
    for (int pi = 0; pi < 2; pi++)
        #pragma unroll
        for (int pj = 0; pj < 2; pj++) {
            float mL = fmaxf(fmaxf(unpack_lo(acc[2*pi][2*pj]),   unpack_lo(acc[2*pi][2*pj+1])),
                             fmaxf(unpack_lo(acc[2*pi+1][2*pj]), unpack_lo(acc[2*pi+1][2*pj+1])));
            float mH = fmaxf(fmaxf(unpack_hi(acc[2*pi][2*pj]),   unpack_hi(acc[2*pi][2*pj+1])),
                             fmaxf(unpack_hi(acc[2*pi+1][2*pj]), unpack_hi(acc[2*pi+1][2*pj+1])));
            float vL = fmaxf(mL + bL, 0.0f);
            float vH = fmaxf(mH + bH, 0.0f);
            int py = ty * 2 + pi, px = tx * 2 + pj;
            outp[(2 * coP) * 16 + py * 4 + px] = vL;
            outp[(2 * coP + 1) * 16 + py * 4 + px] = vH;
        }
}

// ---------------------------------------------------------------------------
// stat3[f] = mean_n pool2[n][f]
// ---------------------------------------------------------------------------
__global__ void k_stat3() {
    int f = blockIdx.x * 32 + threadIdx.x;
    float s = 0.0f;
    for (int nidx = threadIdx.y; nidx < 2048; nidx += 8)
        s += g_pool2[(size_t)nidx * 1024 + f];
    __shared__ float sm[8][32];
    sm[threadIdx.y][threadIdx.x] = s;
    __syncthreads();
    if (threadIdx.y == 0) {
        float tot = 0.0f;
        #pragma unroll
        for (int r = 0; r < 8; r++) tot += sm[r][threadIdx.x];
        g_stat3[f] = tot * (1.0f / 2048.0f);
    }
}

// ---------------------------------------------------------------------------
// Linear effective weights (cond wS2!=0 / bS2!=0; M = max(wM, stat3[f]))
// ---------------------------------------------------------------------------
__global__ void k_w3(const float* __restrict__ w0, const float* __restrict__ wS2,
                     const float* __restrict__ wG, const float* __restrict__ weta,
                     const float* __restrict__ wM,
                     const float* __restrict__ b0, const float* __restrict__ bS2,
                     const float* __restrict__ bG, const float* __restrict__ beta) {
    int tot = gridDim.x * blockDim.x;
    int gid = blockIdx.x * blockDim.x + threadIdx.x;
    for (int i = gid; i < 10240; i += tot) {
        int f = i & 1023;
        float M = fmaxf(wM[i], g_stat3[f]);
        g_w3[i] = scinol_p(w0[i], wS2[i], wG[i], weta[i], M, wS2[i] != 0.0f);
    }
    for (int i = gid; i < 10; i += tot)
        g_b3[i] = scinol_p(b0[i], bS2[i], bG[i], beta[i], 1.0f, bS2[i] != 0.0f);
}

// ---------------------------------------------------------------------------
// Linear: out[n][o] = pool2[n] . w3[o] + b3[o].
// ---------------------------------------------------------------------------
__global__ void __launch_bounds__(320) k_linear(float* __restrict__ out) {
    __shared__ float hs[1024];
    int n = blockIdx.x;
    int tid = threadIdx.x;
    const float* src = g_pool2 + (size_t)n * 1024;
    for (int i = tid; i < 1024; i += 320) hs[i] = src[i];
    __syncthreads();
    int w = tid >> 5, lane = tid & 31;
    const float* wr = g_w3 + w * 1024;
    float s = 0.0f;
    #pragma unroll 8
    for (int k = lane; k < 1024; k += 32) s = fmaf(hs[k], wr[k], s);
    s = warp_sum(s);
    if (lane == 0) out[n * 10 + w] = s + g_b3[w];
}

// ---------------------------------------------------------------------------
// Launch
// ---------------------------------------------------------------------------
extern "C" void kernel_launch(void* const* d_in, const int* in_sizes, int n_in,
                              void* d_out, int out_size) {
    const float* x = (const float*)d_in[0];
    const float* c1_w0 = (const float*)d_in[1];
    const float* c1_wS2 = (const float*)d_in[2];
    const float* c1_wG = (const float*)d_in[3];
    const float* c1_weta = (const float*)d_in[4];
    const float* c1_wM = (const float*)d_in[5];
    const float* c1_b0 = (const float*)d_in[6];
    const float* c1_bS2 = (const float*)d_in[7];
    const float* c1_bG = (const float*)d_in[8];
    const float* c1_beta = (const float*)d_in[9];
    const float* c2_w0 = (const float*)d_in[10];
    const float* c2_wS2 = (const float*)d_in[11];
    const float* c2_wG = (const float*)d_in[12];
    const float* c2_weta = (const float*)d_in[13];
    const float* c2_wM = (const float*)d_in[14];
    const float* c2_b0 = (const float*)d_in[15];
    const float* c2_bS2 = (const float*)d_in[16];
    const float* c2_bG = (const float*)d_in[17];
    const float* c2_beta = (const float*)d_in[18];
    const float* l_w0 = (const float*)d_in[19];
    const float* l_wS2 = (const float*)d_in[20];
    const float* l_wG = (const float*)d_in[21];
    const float* l_weta = (const float*)d_in[22];
    const float* l_wM = (const float*)d_in[23];
    const float* l_b0 = (const float*)d_in[24];
    const float* l_bS2 = (const float*)d_in[25];
    const float* l_bG = (const float*)d_in[26];
    const float* l_beta = (const float*)d_in[27];
    float* out = (float*)d_out;

    k_stat1_max<<<2048, 256>>>(x);
    k_stat1_mean<<<1, 256>>>();
    k_w1<<<8, 256>>>(c1_w0, c1_wS2, c1_wG, c1_weta, c1_wM, c1_b0, c1_bS2, c1_bG, c1_beta);
    k_conv1<<<2048, 128>>>(x);
    k_stat2<<<64, 256>>>();
    k_w2<<<128, 256>>>(c2_w0, c2_wS2, c2_wG, c2_weta, c2_wM, c2_b0, c2_bS2, c2_bG, c2_beta);
    k_conv2<<<2048, 128>>>();
    k_stat3<<<32, dim3(32, 8)>>>();
    k_w3<<<48, 256>>>(l_w0, l_wS2, l_wG, l_weta, l_wM, l_b0, l_bS2, l_bG, l_beta);
    k_linear<<<2048, 320>>>(out);
}

// round 6
// speedup vs baseline: 2.0793x; 2.0033x over previous
#include <cuda_runtime.h>
#include <cuda_bf16.h>
#include <math.h>
#include <stdint.h>

typedef unsigned long long ull;

// ---------------------------------------------------------------------------
// Scratch (device globals — no allocation allowed)
// ---------------------------------------------------------------------------
__device__ ull            g_w1p[25 * 32];      // packed conv1 weights [k][coP]
__device__ float          g_b1[64];
__device__ __nv_bfloat16  g_w2h[25 * 64 * 64]; // conv2 weights hi [pos][co][ci]
__device__ __nv_bfloat16  g_w2l[25 * 64 * 64]; // conv2 weights lo
__device__ float          g_b2[64];
__device__ float          g_w3[10 * 1024];
__device__ float          g_b3[10];
__device__ __nv_bfloat16  g_p1h[(size_t)2048 * 144 * 64];  // pool1 hi, channels-last
__device__ __nv_bfloat16  g_p1l[(size_t)2048 * 144 * 64];  // pool1 lo
__device__ float          g_pool2[(size_t)2048 * 1024];
__device__ float          g_smax1[2048];
__device__ float          g_max2[2048 * 64];
__device__ float          g_stat1;
__device__ float          g_stat2[64];
__device__ float          g_stat3[1024];

// ---------------------------------------------------------------------------
// Helpers
// ---------------------------------------------------------------------------
__device__ __forceinline__ float warp_max(float v) {
    #pragma unroll
    for (int o = 16; o; o >>= 1) v = fmaxf(v, __shfl_xor_sync(0xFFFFFFFFu, v, o));
    return v;
}
__device__ __forceinline__ float warp_sum(float v) {
    #pragma unroll
    for (int o = 16; o; o >>= 1) v += __shfl_xor_sync(0xFFFFFFFFu, v, o);
    return v;
}
__device__ __forceinline__ float scinol_p(float p0, float S2, float G, float eta,
                                          float M, bool cond) {
    float denom = sqrtf(S2 + M * M);
    float theta = fminf(fmaxf(G / denom, -1.0f), 1.0f);
    float upd = cond ? theta / (2.0f * denom) * eta : 0.0f;
    return p0 + upd;
}
__device__ __forceinline__ void fma2(ull& d, ull a, ull b) {
    asm("fma.rn.f32x2 %0, %1, %2, %0;" : "+l"(d) : "l"(a), "l"(b));
}
__device__ __forceinline__ ull pack2(float lo, float hi) {
    return ((ull)__float_as_uint(hi) << 32) | (ull)__float_as_uint(lo);
}
__device__ __forceinline__ float unpack_lo(ull v) { return __uint_as_float((unsigned)v); }
__device__ __forceinline__ float unpack_hi(ull v) { return __uint_as_float((unsigned)(v >> 32)); }

// bf16 HMMA: D(16x8) += A(16x16) * B(16x8), row.col, fp32 accum. sm_80+.
__device__ __forceinline__ void mma16816(float* d, const uint32_t* a, const uint32_t* b) {
    asm volatile(
        "mma.sync.aligned.m16n8k16.row.col.f32.bf16.bf16.f32 "
        "{%0,%1,%2,%3}, {%4,%5,%6,%7}, {%8,%9}, {%0,%1,%2,%3};"
        : "+f"(d[0]), "+f"(d[1]), "+f"(d[2]), "+f"(d[3])
        : "r"(a[0]), "r"(a[1]), "r"(a[2]), "r"(a[3]), "r"(b[0]), "r"(b[1]));
}

// ---------------------------------------------------------------------------
// Stage 1: stat1 = mean_n( max_{h,w} |x[n,0,h,w]| )
// ---------------------------------------------------------------------------
__global__ void k_stat1_max(const float* __restrict__ x) {
    int n = blockIdx.x;
    const float* xp = x + (size_t)n * 784;
    float m = 0.0f;
    for (int i = threadIdx.x; i < 784; i += 256) m = fmaxf(m, fabsf(xp[i]));
    __shared__ float s[8];
    m = warp_max(m);
    if ((threadIdx.x & 31) == 0) s[threadIdx.x >> 5] = m;
    __syncthreads();
    if (threadIdx.x < 32) {
        float v = (threadIdx.x < 8) ? s[threadIdx.x] : 0.0f;
        v = warp_max(v);
        if (threadIdx.x == 0) g_smax1[n] = v;
    }
}

__global__ void k_stat1_mean() {
    float s = 0.0f;
    for (int i = threadIdx.x; i < 2048; i += 256) s += g_smax1[i];
    __shared__ float sm[8];
    s = warp_sum(s);
    if ((threadIdx.x & 31) == 0) sm[threadIdx.x >> 5] = s;
    __syncthreads();
    if (threadIdx.x < 32) {
        float v = (threadIdx.x < 8) ? sm[threadIdx.x] : 0.0f;
        v = warp_sum(v);
        if (threadIdx.x == 0) g_stat1 = v * (1.0f / 2048.0f);
    }
}

// ---------------------------------------------------------------------------
// Conv1 effective weights
// ---------------------------------------------------------------------------
__global__ void k_w1(const float* __restrict__ w0, const float* __restrict__ wS2,
                     const float* __restrict__ wG, const float* __restrict__ weta,
                     const float* __restrict__ wM,
                     const float* __restrict__ b0, const float* __restrict__ bS2,
                     const float* __restrict__ bG, const float* __restrict__ beta) {
    float M = fmaxf(g_stat1, wM[0]);
    int tot = gridDim.x * blockDim.x;
    int gid = blockIdx.x * blockDim.x + threadIdx.x;
    for (int p = gid; p < 800; p += tot) {
        int k = p >> 5, coP = p & 31;
        int iL = (2 * coP) * 25 + k;
        int iH = (2 * coP + 1) * 25 + k;
        float lo = scinol_p(w0[iL], wS2[iL], wG[iL], weta[iL], M, wG[iL] != 0.0f);
        float hi = scinol_p(w0[iH], wS2[iH], wG[iH], weta[iH], M, wG[iH] != 0.0f);
        g_w1p[p] = pack2(lo, hi);
    }
    for (int i = gid; i < 64; i += tot)
        g_b1[i] = scinol_p(b0[i], bS2[i], bG[i], beta[i], 1.0f, bG[i] != 0.0f);
}

// ---------------------------------------------------------------------------
// Conv1 + ReLU + 2x2 maxpool. Output: channels-last bf16 hi/lo split.
// ---------------------------------------------------------------------------
__global__ void __launch_bounds__(128, 4) k_conv1(const float* __restrict__ x) {
    __shared__ ull xs2[784];
    __shared__ ull ws[800];
    int n = blockIdx.x;
    int tid = threadIdx.x;
    const float* xp = x + (size_t)n * 784;
    for (int i = tid; i < 784; i += 128) {
        float v = xp[i];
        xs2[i] = pack2(v, v);
    }
    for (int i = tid; i < 800; i += 128) ws[i] = g_w1p[i];
    __syncthreads();

    int coP = tid >> 2, q = tid & 3;
    float bL = g_b1[2 * coP], bH = g_b1[2 * coP + 1];
    float cmaxL = 0.0f, cmaxH = 0.0f;
    size_t nbase = (size_t)n * 144;

    for (int t = q; t < 36; t += 4) {
        int tr = t / 6, tc = t - tr * 6;
        const ull* xc = xs2 + (tr * 4) * 28 + tc * 4;
        ull X[4][8];
        #pragma unroll
        for (int r = 0; r < 4; r++)
            #pragma unroll
            for (int c2 = 0; c2 < 4; c2++) {
                ulonglong2 v2 = *(const ulonglong2*)(xc + r * 28 + 2 * c2);
                X[r][2 * c2] = v2.x;
                X[r][2 * c2 + 1] = v2.y;
            }
        ull acc[4][4];
        #pragma unroll
        for (int i = 0; i < 4; i++)
            #pragma unroll
            for (int j = 0; j < 4; j++) acc[i][j] = 0ULL;

        #pragma unroll
        for (int ky = 0; ky < 5; ky++) {
            ull w[5];
            #pragma unroll
            for (int kx = 0; kx < 5; kx++)
                w[kx] = ws[(ky * 5 + kx) * 32 + coP];
            #pragma unroll
            for (int kx = 0; kx < 5; kx++)
                #pragma unroll
                for (int i = 0; i < 4; i++)
                    #pragma unroll
                    for (int j = 0; j < 4; j++)
                        fma2(acc[i][j], w[kx], X[(ky + i) & 3][j + kx]);
            if (ky < 4) {
                #pragma unroll
                for (int c2 = 0; c2 < 4; c2++) {
                    ulonglong2 v2 = *(const ulonglong2*)(xc + (ky + 4) * 28 + 2 * c2);
                    X[ky & 3][2 * c2] = v2.x;
                    X[ky & 3][2 * c2 + 1] = v2.y;
                }
            }
        }

        #pragma unroll
        for (int pi = 0; pi < 2; pi++)
            #pragma unroll
            for (int pj = 0; pj < 2; pj++) {
                float mL = fmaxf(fmaxf(unpack_lo(acc[2*pi][2*pj]),   unpack_lo(acc[2*pi][2*pj+1])),
                                 fmaxf(unpack_lo(acc[2*pi+1][2*pj]), unpack_lo(acc[2*pi+1][2*pj+1])));
                float mH = fmaxf(fmaxf(unpack_hi(acc[2*pi][2*pj]),   unpack_hi(acc[2*pi][2*pj+1])),
                                 fmaxf(unpack_hi(acc[2*pi+1][2*pj]), unpack_hi(acc[2*pi+1][2*pj+1])));
                float vL = fmaxf(mL + bL, 0.0f);
                float vH = fmaxf(mH + bH, 0.0f);
                int rowpix = (tr * 2 + pi) * 12 + (tc * 2 + pj);
                size_t base = (nbase + rowpix) * 64;
                __nv_bfloat16 hL = __float2bfloat16(vL);
                __nv_bfloat16 hH = __float2bfloat16(vH);
                g_p1h[base + 2 * coP]     = hL;
                g_p1h[base + 2 * coP + 1] = hH;
                g_p1l[base + 2 * coP]     = __float2bfloat16(vL - __bfloat162float(hL));
                g_p1l[base + 2 * coP + 1] = __float2bfloat16(vH - __bfloat162float(hH));
                cmaxL = fmaxf(cmaxL, vL);
                cmaxH = fmaxf(cmaxH, vH);
            }
    }
    cmaxL = fmaxf(cmaxL, __shfl_xor_sync(0xFFFFFFFFu, cmaxL, 1));
    cmaxL = fmaxf(cmaxL, __shfl_xor_sync(0xFFFFFFFFu, cmaxL, 2));
    cmaxH = fmaxf(cmaxH, __shfl_xor_sync(0xFFFFFFFFu, cmaxH, 1));
    cmaxH = fmaxf(cmaxH, __shfl_xor_sync(0xFFFFFFFFu, cmaxH, 2));
    if (q == 0) {
        g_max2[n * 64 + 2 * coP] = cmaxL;
        g_max2[n * 64 + 2 * coP + 1] = cmaxH;
    }
}

// ---------------------------------------------------------------------------
// stat2[c] = mean_n g_max2[n][c]
// ---------------------------------------------------------------------------
__global__ void k_stat2() {
    int c = blockIdx.x;
    float s = 0.0f;
    for (int i = threadIdx.x; i < 2048; i += 256) s += g_max2[i * 64 + c];
    __shared__ float sm[8];
    s = warp_sum(s);
    if ((threadIdx.x & 31) == 0) sm[threadIdx.x >> 5] = s;
    __syncthreads();
    if (threadIdx.x < 32) {
        float v = (threadIdx.x < 8) ? sm[threadIdx.x] : 0.0f;
        v = warp_sum(v);
        if (threadIdx.x == 0) g_stat2[c] = v * (1.0f / 2048.0f);
    }
}

// ---------------------------------------------------------------------------
// Conv2 effective weights -> bf16 hi/lo in layout [pos][co][ci]
// ---------------------------------------------------------------------------
__global__ void k_w2(const float* __restrict__ w0, const float* __restrict__ wS2,
                     const float* __restrict__ wG, const float* __restrict__ weta,
                     const float* __restrict__ wM,
                     const float* __restrict__ b0, const float* __restrict__ bS2,
                     const float* __restrict__ bG, const float* __restrict__ beta) {
    int tot = gridDim.x * blockDim.x;
    int gid = blockIdx.x * blockDim.x + threadIdx.x;
    for (int p = gid; p < 102400; p += tot) {
        int ci = p & 63;
        int co = (p >> 6) & 63;
        int pos = p >> 12;
        int ky = pos / 5, kx = pos - ky * 5;
        float M = fmaxf(g_stat2[ci], wM[ci]);
        int src = (co * 64 + ci) * 25 + ky * 5 + kx;
        float w = scinol_p(w0[src], wS2[src], wG[src], weta[src], M, wG[src] != 0.0f);
        __nv_bfloat16 h = __float2bfloat16(w);
        g_w2h[p] = h;
        g_w2l[p] = __float2bfloat16(w - __bfloat162float(h));
    }
    for (int i = gid; i < 64; i += tot)
        g_b2[i] = scinol_p(b0[i], bS2[i], bG[i], beta[i], 1.0f, bG[i] != 0.0f);
}

// ---------------------------------------------------------------------------
// Conv2 via mma.sync bf16 split-precision implicit GEMM (sm_80+ HMMA).
// CTA = 2 samples, 8 warps: wm = wid&3 (M blocks of 32 pixels), wn = wid>>2
// (N blocks of 32 co). Full input window staged in smem once (hi/lo, row
// stride 72 bf16 = 144B for conflict-free fragment LDS); B tile (16KB)
// staged per kernel position.
// Dyn smem bytes: WIN_H 0..41471, WIN_L 41472.., B_H 82944.., B_L 92160..101375
// ---------------------------------------------------------------------------
__global__ void __launch_bounds__(256, 2) k_conv2() {
    extern __shared__ char smc[];
    char* winH = smc;
    char* winL = smc + 41472;
    char* BH   = smc + 82944;
    char* BL   = smc + 92160;

    int tid = threadIdx.x;
    int wid = tid >> 5, lane = tid & 31;
    int n2 = blockIdx.x;
    int wm = wid & 3, wn = wid >> 2;
    int r4 = lane >> 2, c4 = lane & 3;

    // ---- stage input window: 288 rows (2 samples x 144 pix) x 64 bf16 ----
    {
        const uint2* sh = (const uint2*)g_p1h + (size_t)n2 * 288 * 16;
        const uint2* sl = (const uint2*)g_p1l + (size_t)n2 * 288 * 16;
        for (int i = tid; i < 4608; i += 256) {
            int row = i >> 4, c8 = i & 15;
            uint32_t off = (uint32_t)row * 144 + c8 * 8;
            *(uint2*)(winH + off) = sh[i];
            *(uint2*)(winL + off) = sl[i];
        }
    }

    float acc[2][4][4];
    #pragma unroll
    for (int t = 0; t < 2; t++)
        #pragma unroll
        for (int nt = 0; nt < 4; nt++)
            #pragma unroll
            for (int e = 0; e < 4; e++) acc[t][nt][e] = 0.0f;

    // B fragment row offsets (fixed across pos): n = wn*32 + nt*8 + r4
    uint32_t brow[4];
    #pragma unroll
    for (int nt = 0; nt < 4; nt++) brow[nt] = (uint32_t)(wn * 32 + nt * 8 + r4) * 144;

    const uint2* w2h2 = (const uint2*)g_w2h;
    const uint2* w2l2 = (const uint2*)g_w2l;

    for (int pos = 0; pos < 25; pos++) {
        int ky = pos / 5, kx = pos - ky * 5;

        __syncthreads();   // previous pos's mma reads of B done
        {   // stage B tile: 64 rows x 64 bf16 (hi, lo) = 1024 uint2 each
            size_t base = (size_t)pos * 1024;
            #pragma unroll
            for (int j = 0; j < 4; j++) {
                int i = tid + j * 256;
                int row = i >> 4, c8 = i & 15;
                uint32_t off = (uint32_t)row * 144 + c8 * 8;
                *(uint2*)(BH + off) = w2h2[base + i];
                *(uint2*)(BL + off) = w2l2[base + i];
            }
        }
        __syncthreads();

        // A fragment row byte-offsets for this pos: m = wm*32 + t*16 + r4 (+8)
        uint32_t arow[2][2];
        #pragma unroll
        for (int t = 0; t < 2; t++) {
            int m = wm * 32 + t * 16 + r4;
            int s_ = m >> 6, oy = (m >> 3) & 7, ox = m & 7;
            int pix = s_ * 144 + (oy + ky) * 12 + (ox + kx);
            arow[t][0] = (uint32_t)pix * 144;
            arow[t][1] = (uint32_t)(pix + 12) * 144;   // m+8 -> oy+1
        }

        #pragma unroll
        for (int ks = 0; ks < 4; ks++) {
            uint32_t kb = (uint32_t)(ks * 32 + c4 * 4);
            uint32_t ah[2][4], al[2][4], bh[4][2], bl[4][2];
            #pragma unroll
            for (int t = 0; t < 2; t++) {
                ah[t][0] = *(const uint32_t*)(winH + arow[t][0] + kb);
                ah[t][1] = *(const uint32_t*)(winH + arow[t][1] + kb);
                ah[t][2] = *(const uint32_t*)(winH + arow[t][0] + kb + 16);
                ah[t][3] = *(const uint32_t*)(winH + arow[t][1] + kb + 16);
                al[t][0] = *(const uint32_t*)(winL + arow[t][0] + kb);
                al[t][1] = *(const uint32_t*)(winL + arow[t][1] + kb);
                al[t][2] = *(const uint32_t*)(winL + arow[t][0] + kb + 16);
                al[t][3] = *(const uint32_t*)(winL + arow[t][1] + kb + 16);
            }
            #pragma unroll
            for (int nt = 0; nt < 4; nt++) {
                bh[nt][0] = *(const uint32_t*)(BH + brow[nt] + kb);
                bh[nt][1] = *(const uint32_t*)(BH + brow[nt] + kb + 16);
                bl[nt][0] = *(const uint32_t*)(BL + brow[nt] + kb);
                bl[nt][1] = *(const uint32_t*)(BL + brow[nt] + kb + 16);
            }
            #pragma unroll
            for (int t = 0; t < 2; t++)
                #pragma unroll
                for (int nt = 0; nt < 4; nt++) {
                    mma16816(acc[t][nt], ah[t], bh[nt]);
                    mma16816(acc[t][nt], ah[t], bl[nt]);
                    mma16816(acc[t][nt], al[t], bh[nt]);
                }
        }
    }

    // ---- epilogue: 2x2 maxpool + bias + relu ----
    // c-frag rows r4 (oy even) and r4+8 (oy odd) are the oy-pool pair;
    // ox-pool partner is lane^4 (r4^1). Active writers: r4 even.
    int m0 = wm * 32 + r4;            // tile t adds +16
    bool act = (r4 & 1) == 0;
    #pragma unroll
    for (int t = 0; t < 2; t++) {
        int m = m0 + t * 16;
        int s_ = m >> 6;
        int py = (m >> 4) & 3;
        int px = (r4 >> 1) & 3;
        float* outp = g_pool2 + (size_t)(n2 * 2 + s_) * 1024 + py * 4 + px;
        #pragma unroll
        for (int nt = 0; nt < 4; nt++) {
            float p0 = fmaxf(acc[t][nt][0], acc[t][nt][2]);
            float p1 = fmaxf(acc[t][nt][1], acc[t][nt][3]);
            float q0 = fmaxf(p0, __shfl_xor_sync(0xFFFFFFFFu, p0, 4));
            float q1 = fmaxf(p1, __shfl_xor_sync(0xFFFFFFFFu, p1, 4));
            if (act) {
                int co = wn * 32 + nt * 8 + c4 * 2;
                outp[co * 16]       = fmaxf(q0 + __ldg(g_b2 + co), 0.0f);
                outp[(co + 1) * 16] = fmaxf(q1 + __ldg(g_b2 + co + 1), 0.0f);
            }
        }
    }
}

// ---------------------------------------------------------------------------
// stat3[f] = mean_n pool2[n][f]
// ---------------------------------------------------------------------------
__global__ void k_stat3() {
    int f = blockIdx.x * 32 + threadIdx.x;
    float s = 0.0f;
    for (int nidx = threadIdx.y; nidx < 2048; nidx += 8)
        s += g_pool2[(size_t)nidx * 1024 + f];
    __shared__ float sm[8][32];
    sm[threadIdx.y][threadIdx.x] = s;
    __syncthreads();
    if (threadIdx.y == 0) {
        float tot = 0.0f;
        #pragma unroll
        for (int r = 0; r < 8; r++) tot += sm[r][threadIdx.x];
        g_stat3[f] = tot * (1.0f / 2048.0f);
    }
}

// ---------------------------------------------------------------------------
// Linear effective weights (cond wS2!=0 / bS2!=0)
// ---------------------------------------------------------------------------
__global__ void k_w3(const float* __restrict__ w0, const float* __restrict__ wS2,
                     const float* __restrict__ wG, const float* __restrict__ weta,
                     const float* __restrict__ wM,
                     const float* __restrict__ b0, const float* __restrict__ bS2,
                     const float* __restrict__ bG, const float* __restrict__ beta) {
    int tot = gridDim.x * blockDim.x;
    int gid = blockIdx.x * blockDim.x + threadIdx.x;
    for (int i = gid; i < 10240; i += tot) {
        int f = i & 1023;
        float M = fmaxf(wM[i], g_stat3[f]);
        g_w3[i] = scinol_p(w0[i], wS2[i], wG[i], weta[i], M, wS2[i] != 0.0f);
    }
    for (int i = gid; i < 10; i += tot)
        g_b3[i] = scinol_p(b0[i], bS2[i], bG[i], beta[i], 1.0f, bS2[i] != 0.0f);
}

// ---------------------------------------------------------------------------
// Linear
// ---------------------------------------------------------------------------
__global__ void __launch_bounds__(320) k_linear(float* __restrict__ out) {
    __shared__ float hs[1024];
    int n = blockIdx.x;
    int tid = threadIdx.x;
    const float* src = g_pool2 + (size_t)n * 1024;
    for (int i = tid; i < 1024; i += 320) hs[i] = src[i];
    __syncthreads();
    int w = tid >> 5, lane = tid & 31;
    const float* wr = g_w3 + w * 1024;
    float s = 0.0f;
    #pragma unroll 8
    for (int k = lane; k < 1024; k += 32) s = fmaf(hs[k], wr[k], s);
    s = warp_sum(s);
    if (lane == 0) out[n * 10 + w] = s + g_b3[w];
}

// ---------------------------------------------------------------------------
// Launch
// ---------------------------------------------------------------------------
extern "C" void kernel_launch(void* const* d_in, const int* in_sizes, int n_in,
                              void* d_out, int out_size) {
    const float* x = (const float*)d_in[0];
    const float* c1_w0 = (const float*)d_in[1];
    const float* c1_wS2 = (const float*)d_in[2];
    const float* c1_wG = (const float*)d_in[3];
    const float* c1_weta = (const float*)d_in[4];
    const float* c1_wM = (const float*)d_in[5];
    const float* c1_b0 = (const float*)d_in[6];
    const float* c1_bS2 = (const float*)d_in[7];
    const float* c1_bG = (const float*)d_in[8];
    const float* c1_beta = (const float*)d_in[9];
    const float* c2_w0 = (const float*)d_in[10];
    const float* c2_wS2 = (const float*)d_in[11];
    const float* c2_wG = (const float*)d_in[12];
    const float* c2_weta = (const float*)d_in[13];
    const float* c2_wM = (const float*)d_in[14];
    const float* c2_b0 = (const float*)d_in[15];
    const float* c2_bS2 = (const float*)d_in[16];
    const float* c2_bG = (const float*)d_in[17];
    const float* c2_beta = (const float*)d_in[18];
    const float* l_w0 = (const float*)d_in[19];
    const float* l_wS2 = (const float*)d_in[20];
    const float* l_wG = (const float*)d_in[21];
    const float* l_weta = (const float*)d_in[22];
    const float* l_wM = (const float*)d_in[23];
    const float* l_b0 = (const float*)d_in[24];
    const float* l_bS2 = (const float*)d_in[25];
    const float* l_bG = (const float*)d_in[26];
    const float* l_beta = (const float*)d_in[27];
    float* out = (float*)d_out;

    cudaFuncSetAttribute(k_conv2, cudaFuncAttributeMaxDynamicSharedMemorySize, 101376);

    k_stat1_max<<<2048, 256>>>(x);
    k_stat1_mean<<<1, 256>>>();
    k_w1<<<8, 256>>>(c1_w0, c1_wS2, c1_wG, c1_weta, c1_wM, c1_b0, c1_bS2, c1_bG, c1_beta);
    k_conv1<<<2048, 128>>>(x);
    k_stat2<<<64, 256>>>();
    k_w2<<<160, 256>>>(c2_w0, c2_wS2, c2_wG, c2_weta, c2_wM, c2_b0, c2_bS2, c2_bG, c2_beta);
    k_conv2<<<1024, 256, 101376>>>();
    k_stat3<<<32, dim3(32, 8)>>>();
    k_w3<<<48, 256>>>(l_w0, l_wS2, l_wG, l_weta, l_wM, l_b0, l_bS2, l_bG, l_beta);
    k_linear<<<2048, 320>>>(out);
}